// round 4
// baseline (speedup 1.0000x reference)
#include <cuda_runtime.h>

// ---------------------------------------------------------------------------
// GraphSAGE 2-layer mean-aggregator forward.
//   m2  = mean_10(feats[ids2])                        [12800,256]
//   h1  = relu([feats[ids1]@Wx1+bx1 ; m2@Wn1+bn1])    [12800,256]
//   m1  = mean_25(feats[ids1])                        [512,256]
//   mh1 = mean_25(h1)                                 [512,256]
//   h0  = relu([feats[ids]@Wx1+bx1 ; m1@Wn1+bn1])     [512,256]
//   g0  = [h0@Wx2+bx2 ; mh1@Wn2+bn2]                  [512,256]
//   out = (g0 / max(||g0||_row, 1e-12)) @ Wfc + bfc   [512,7]
// ---------------------------------------------------------------------------

#define NB     512          // batch B
#define S0V    25
#define S1V    10
#define DIM    256          // IN_DIM == 2*HID
#define HIDV   128
#define M1ROWS (NB * S0V)   // 12800

// scratch (static device globals; no allocation allowed)
__device__ float g_m2 [M1ROWS * DIM];   // 13.1 MB
__device__ float g_h1 [M1ROWS * DIM];   // 13.1 MB
__device__ float g_m1 [NB * DIM];
__device__ float g_mh1[NB * DIM];
__device__ float g_h0 [NB * DIM];
__device__ float g_g0 [NB * DIM];

// ---------------------------------------------------------------------------
// Gather/mean: one warp per output row; lane handles 8 cols as 2x float4.
// GATHER=true: rows come from ids[warp*K+j]; else contiguous warp*K+j.
// ---------------------------------------------------------------------------
template <int K, bool GATHER>
__global__ __launch_bounds__(256)
void mean_kernel(const float* __restrict__ src, const int* __restrict__ ids,
                 float* __restrict__ out, int rows, float inv)
{
    int warp = (blockIdx.x * (blockDim.x >> 5)) + (threadIdx.x >> 5);
    if (warp >= rows) return;
    int lane = threadIdx.x & 31;

    float4 a0 = make_float4(0.f, 0.f, 0.f, 0.f);
    float4 a1 = a0;

#pragma unroll
    for (int j = 0; j < K; ++j) {
        long r = GATHER ? (long)__ldg(&ids[(long)warp * K + j])
                        : ((long)warp * K + j);
        const float4* rp = reinterpret_cast<const float4*>(src + r * DIM);
        float4 v0 = __ldg(rp + lane);
        float4 v1 = __ldg(rp + lane + 32);
        a0.x += v0.x; a0.y += v0.y; a0.z += v0.z; a0.w += v0.w;
        a1.x += v1.x; a1.y += v1.y; a1.z += v1.z; a1.w += v1.w;
    }
    a0.x *= inv; a0.y *= inv; a0.z *= inv; a0.w *= inv;
    a1.x *= inv; a1.y *= inv; a1.z *= inv; a1.w *= inv;

    float4* op = reinterpret_cast<float4*>(out + (long)warp * DIM);
    op[lane]      = a0;
    op[lane + 32] = a1;
}

// ---------------------------------------------------------------------------
// Layer-1 GEMM (the flop hot spot): 12800x128x256 twice (half 0: A = gathered
// feats rows via ids1; half 1: A = g_m2). Classic 128x128x8 fp32 SGEMM tile,
// 256 threads, 8x8 per-thread microtile, relu epilogue into g_h1.
// ---------------------------------------------------------------------------
__global__ __launch_bounds__(256)
void layer1_gemm(const float* __restrict__ feats, const int* __restrict__ ids1,
                 const float* __restrict__ Wx, const float* __restrict__ bx,
                 const float* __restrict__ Wn, const float* __restrict__ bn)
{
    const int half = blockIdx.y;
    const int m0   = blockIdx.x * 128;
    const float* __restrict__ W    = half ? Wn : Wx;
    const float* __restrict__ bias = half ? bn : bx;

    __shared__ float As[8][132];        // transposed A tile (+pad)
    __shared__ float Bs[8][128];
    __shared__ const float* rowp[128];

    const int tid = threadIdx.x;
    if (tid < 128) {
        rowp[tid] = half ? (g_m2 + (long)(m0 + tid) * DIM)
                         : (feats + (long)__ldg(&ids1[m0 + tid]) * DIM);
    }
    __syncthreads();

    // loader mapping
    const int la_m = tid >> 1;          // 0..127
    const int la_k = (tid & 1) * 4;     // 0 or 4
    const int lb_k = tid >> 5;          // 0..7
    const int lb_c = (tid & 31) * 4;    // 0..124
    // compute mapping
    const int tx = tid & 15;
    const int ty = tid >> 4;

    const float* arow = rowp[la_m];

    float acc[8][8];
#pragma unroll
    for (int i = 0; i < 8; ++i)
#pragma unroll
        for (int j = 0; j < 8; ++j) acc[i][j] = 0.f;

    for (int k0 = 0; k0 < DIM; k0 += 8) {
        float4 av = *reinterpret_cast<const float4*>(arow + k0 + la_k);
        float4 bv = *reinterpret_cast<const float4*>(W + (long)(k0 + lb_k) * HIDV + lb_c);
        As[la_k + 0][la_m] = av.x;
        As[la_k + 1][la_m] = av.y;
        As[la_k + 2][la_m] = av.z;
        As[la_k + 3][la_m] = av.w;
        *reinterpret_cast<float4*>(&Bs[lb_k][lb_c]) = bv;
        __syncthreads();

#pragma unroll
        for (int kk = 0; kk < 8; ++kk) {
            float4 aA = *reinterpret_cast<const float4*>(&As[kk][ty * 8]);
            float4 aB = *reinterpret_cast<const float4*>(&As[kk][ty * 8 + 4]);
            float4 bA = *reinterpret_cast<const float4*>(&Bs[kk][tx * 8]);
            float4 bB = *reinterpret_cast<const float4*>(&Bs[kk][tx * 8 + 4]);
            float a[8] = {aA.x, aA.y, aA.z, aA.w, aB.x, aB.y, aB.z, aB.w};
            float b[8] = {bA.x, bA.y, bA.z, bA.w, bB.x, bB.y, bB.z, bB.w};
#pragma unroll
            for (int i = 0; i < 8; ++i)
#pragma unroll
                for (int j = 0; j < 8; ++j)
                    acc[i][j] = fmaf(a[i], b[j], acc[i][j]);
        }
        __syncthreads();
    }

    float bv8[8];
#pragma unroll
    for (int j = 0; j < 8; ++j) bv8[j] = bias[tx * 8 + j];

#pragma unroll
    for (int i = 0; i < 8; ++i) {
        float4 o0, o1;
        o0.x = fmaxf(acc[i][0] + bv8[0], 0.f);
        o0.y = fmaxf(acc[i][1] + bv8[1], 0.f);
        o0.z = fmaxf(acc[i][2] + bv8[2], 0.f);
        o0.w = fmaxf(acc[i][3] + bv8[3], 0.f);
        o1.x = fmaxf(acc[i][4] + bv8[4], 0.f);
        o1.y = fmaxf(acc[i][5] + bv8[5], 0.f);
        o1.z = fmaxf(acc[i][6] + bv8[6], 0.f);
        o1.w = fmaxf(acc[i][7] + bv8[7], 0.f);
        float* dst = g_h1 + (long)(m0 + ty * 8 + i) * DIM + half * HIDV + tx * 8;
        *reinterpret_cast<float4*>(dst)     = o0;
        *reinterpret_cast<float4*>(dst + 4) = o1;
    }
}

// ---------------------------------------------------------------------------
// Small concat-GEMM (512 rows): out[row] = act([x@Wx+bx ; m@Wn+bn]).
// One block per row, 256 threads, thread t computes one output column.
// ---------------------------------------------------------------------------
__global__ __launch_bounds__(256)
void small_agg(const float* __restrict__ xsrc, const int* __restrict__ ids,
               const float* __restrict__ msrc,
               const float* __restrict__ Wx, const float* __restrict__ bx,
               const float* __restrict__ Wn, const float* __restrict__ bn,
               float* __restrict__ out, int do_relu)
{
    const int row = blockIdx.x;
    __shared__ float sx[DIM];
    __shared__ float sm[DIM];
    const int t = threadIdx.x;

    const float* xrow = ids ? (xsrc + (long)__ldg(&ids[row]) * DIM)
                            : (xsrc + (long)row * DIM);
    sx[t] = __ldg(&xrow[t]);
    sm[t] = msrc[(long)row * DIM + t];
    __syncthreads();

    const int half = t >> 7;
    const int col  = t & 127;
    const float* __restrict__ W = half ? Wn : Wx;
    const float* __restrict__ s = half ? sm : sx;

    float acc = 0.f;
#pragma unroll 8
    for (int k = 0; k < DIM; ++k)
        acc = fmaf(s[k], __ldg(&W[k * HIDV + col]), acc);

    acc += half ? bn[col] : bx[col];
    if (do_relu) acc = fmaxf(acc, 0.f);
    out[(long)row * DIM + t] = acc;
}

// ---------------------------------------------------------------------------
// Final: row-normalize g0 then tiny FC [256 -> 7]. One block per row.
// ---------------------------------------------------------------------------
__global__ __launch_bounds__(256)
void final_kernel(const float* __restrict__ g0, const float* __restrict__ Wfc,
                  const float* __restrict__ bfc, float* __restrict__ out)
{
    const int row = blockIdx.x;
    __shared__ float s[DIM];
    __shared__ float red[8];
    __shared__ float s_inv;
    const int t = threadIdx.x;

    float v = g0[(long)row * DIM + t];
    s[t] = v;
    float sq = v * v;
#pragma unroll
    for (int o = 16; o; o >>= 1) sq += __shfl_xor_sync(0xFFFFFFFFu, sq, o);
    if ((t & 31) == 0) red[t >> 5] = sq;
    __syncthreads();
    if (t == 0) {
        float tot = 0.f;
#pragma unroll
        for (int i = 0; i < 8; ++i) tot += red[i];
        s_inv = 1.f / fmaxf(sqrtf(tot), 1e-12f);
    }
    __syncthreads();
    const float inv = s_inv;

    const int w = t >> 5, l = t & 31;
    if (w < 7) {
        float acc = 0.f;
#pragma unroll
        for (int k = l; k < DIM; k += 32)
            acc = fmaf(s[k], __ldg(&Wfc[k * 7 + w]), acc);
#pragma unroll
        for (int o = 16; o; o >>= 1) acc += __shfl_xor_sync(0xFFFFFFFFu, acc, o);
        if (l == 0) out[row * 7 + w] = acc * inv + bfc[w];
    }
}

// ---------------------------------------------------------------------------
extern "C" void kernel_launch(void* const* d_in, const int* in_sizes, int n_in,
                              void* d_out, int out_size)
{
    const int*   ids   = (const int*)  d_in[0];
    const int*   ids1  = (const int*)  d_in[1];
    const int*   ids2  = (const int*)  d_in[2];
    const float* feats = (const float*)d_in[3];
    const float* Wx1   = (const float*)d_in[4];
    const float* bx1   = (const float*)d_in[5];
    const float* Wn1   = (const float*)d_in[6];
    const float* bn1   = (const float*)d_in[7];
    const float* Wx2   = (const float*)d_in[8];
    const float* bx2   = (const float*)d_in[9];
    const float* Wn2   = (const float*)d_in[10];
    const float* bn2   = (const float*)d_in[11];
    const float* Wfc   = (const float*)d_in[12];
    const float* bfc   = (const float*)d_in[13];
    float* out = (float*)d_out;

    float *m2, *h1, *m1, *mh1, *h0, *g0;
    cudaGetSymbolAddress((void**)&m2,  g_m2);
    cudaGetSymbolAddress((void**)&h1,  g_h1);
    cudaGetSymbolAddress((void**)&m1,  g_m1);
    cudaGetSymbolAddress((void**)&mh1, g_mh1);
    cudaGetSymbolAddress((void**)&h0,  g_h0);
    cudaGetSymbolAddress((void**)&g0,  g_g0);

    // 1) m2[12800,256] = mean_10(feats[ids2])  — heavy gather (131 MB)
    mean_kernel<S1V, true><<<(M1ROWS * 32 + 255) / 256, 256>>>(feats, ids2, m2, M1ROWS, 1.f / S1V);
    // 2) m1[512,256] = mean_25(feats[ids1])
    mean_kernel<S0V, true><<<(NB * 32 + 255) / 256, 256>>>(feats, ids1, m1, NB, 1.f / S0V);
    // 3) h1 = relu([f1@Wx1 ; m2@Wn1])  — flop hot spot
    dim3 grid(M1ROWS / 128, 2);
    layer1_gemm<<<grid, 256>>>(feats, ids1, Wx1, bx1, Wn1, bn1);
    // 4) mh1[512,256] = mean_25(h1) (contiguous rows)
    mean_kernel<S0V, false><<<(NB * 32 + 255) / 256, 256>>>(h1, nullptr, mh1, NB, 1.f / S0V);
    // 5) h0 = relu([f0@Wx1 ; m1@Wn1])
    small_agg<<<NB, 256>>>(feats, ids, m1, Wx1, bx1, Wn1, bn1, h0, 1);
    // 6) g0 = [h0@Wx2 ; mh1@Wn2]   (no activation)
    small_agg<<<NB, 256>>>(h0, nullptr, mh1, Wx2, bx2, Wn2, bn2, g0, 0);
    // 7) out = normalize(g0) @ Wfc + bfc
    final_kernel<<<NB, 256>>>(g0, Wfc, bfc, out);
}

// round 6
// speedup vs baseline: 1.0497x; 1.0497x over previous
#include <cuda_runtime.h>
#include <cuda_bf16.h>
#include <cstdint>

// ---------------------------------------------------------------------------
// GraphSAGE 2-layer mean-aggregator forward, mma.sync(bf16 hi/lo split) GEMMs.
//   m1  = mean_25(feats[ids1])                                  [512,256]
//   mh1 = mean_25(relu([f1@Wx1+bx1 ; mean10(feats[ids2])@Wn1+bn1]))  (fused:
//         m2 gather-mean folded into GEMM A-loader; h1 never stored)
//   h0  = relu([feats[ids]@Wx1+bx1 ; m1@Wn1+bn1])               [512,256]
//   g0  = [h0@Wx2+bx2 ; mh1@Wn2+bn2]                            [512,256]
//   out = (g0 / max(||g0||,1e-12)) @ Wfc + bfc                  [512,7]
// ---------------------------------------------------------------------------

#define NB     512
#define S0V    25
#define DIM    256
#define HIDV   128
#define M1ROWS (NB * S0V)   // 12800

__device__ float g_m1 [NB * DIM];
__device__ float g_mh1[NB * DIM];
__device__ float g_h0 [NB * DIM];
__device__ float g_g0 [NB * DIM];

// ---------------------------------------------------------------------------
// helpers
// ---------------------------------------------------------------------------
__device__ __forceinline__ uint32_t smem_u32(const void* p) {
    uint32_t a;
    asm("{ .reg .u64 t; cvta.to.shared.u64 t, %1; cvt.u32.u64 %0, t; }" : "=r"(a) : "l"(p));
    return a;
}
__device__ __forceinline__ uint32_t packbf(__nv_bfloat16 a, __nv_bfloat16 b) {
    __nv_bfloat162 t(a, b);
    return *reinterpret_cast<uint32_t*>(&t);
}
// split float4 into bf16 hi tile + bf16 residual tile, store 8B each
__device__ __forceinline__ void split_store(void* ph, void* pl, float4 v) {
    __nv_bfloat16 hx = __float2bfloat16_rn(v.x);
    __nv_bfloat16 hy = __float2bfloat16_rn(v.y);
    __nv_bfloat16 hz = __float2bfloat16_rn(v.z);
    __nv_bfloat16 hw = __float2bfloat16_rn(v.w);
    __nv_bfloat16 lx = __float2bfloat16_rn(v.x - __bfloat162float(hx));
    __nv_bfloat16 ly = __float2bfloat16_rn(v.y - __bfloat162float(hy));
    __nv_bfloat16 lz = __float2bfloat16_rn(v.z - __bfloat162float(hz));
    __nv_bfloat16 lw = __float2bfloat16_rn(v.w - __bfloat162float(hw));
    *reinterpret_cast<uint2*>(ph) = make_uint2(packbf(hx, hy), packbf(hz, hw));
    *reinterpret_cast<uint2*>(pl) = make_uint2(packbf(lx, ly), packbf(lz, lw));
}
__device__ __forceinline__ void ldsm4(uint32_t* r, uint32_t addr) {
    asm volatile("ldmatrix.sync.aligned.m8n8.x4.shared.b16 {%0,%1,%2,%3}, [%4];"
        : "=r"(r[0]), "=r"(r[1]), "=r"(r[2]), "=r"(r[3]) : "r"(addr));
}
__device__ __forceinline__ void ldsm2t(uint32_t* r, uint32_t addr) {
    asm volatile("ldmatrix.sync.aligned.m8n8.x2.trans.shared.b16 {%0,%1}, [%2];"
        : "=r"(r[0]), "=r"(r[1]) : "r"(addr));
}
__device__ __forceinline__ void mma16816(float* d, const uint32_t* a, const uint32_t* b) {
    asm volatile("mma.sync.aligned.m16n8k16.row.col.f32.bf16.bf16.f32 "
        "{%0,%1,%2,%3},{%4,%5,%6,%7},{%8,%9},{%0,%1,%2,%3};"
        : "+f"(d[0]), "+f"(d[1]), "+f"(d[2]), "+f"(d[3])
        : "r"(a[0]), "r"(a[1]), "r"(a[2]), "r"(a[3]), "r"(b[0]), "r"(b[1]));
}

// ---------------------------------------------------------------------------
// Unified GEMM: out_block = A[128 rows, 256] @ W[256, NP cols of 128] (+bias)
// MODE 0: l1 fused  — A half0 = feats[ids1] (gather), half1 = mean10(feats[ids2])
//                     epilogue: relu + group-25 column mean -> atomicAdd(mh1)
// MODE 1: h0        — A half0 = feats[ids] (gather), half1 = m1; relu store
// MODE 2: g0        — A half0 = h0, half1 = mh1; plain store
// grid: (M/128, 2 halves, 128/NP col tiles). 256 threads, 8 warps (4M x 2N).
// bf16 hi/lo split: D = Ah*Bh + Ah*Bl + Al*Bh  (fp32 accum).
// ---------------------------------------------------------------------------
template <int MODE, int NP>
__global__ __launch_bounds__(256, 1)
void gemm_k(const float* __restrict__ xsrc, const int* __restrict__ xids,
            const float* __restrict__ msrc, const int* __restrict__ mids,
            const float* __restrict__ Wx, const float* __restrict__ bx,
            const float* __restrict__ Wn, const float* __restrict__ bn,
            float* __restrict__ outp)
{
    constexpr int ASTR = 144;                    // A row stride bytes (72 halves)
    constexpr int BSTR = (NP == 128) ? 272 : 80; // B k-row stride bytes
    constexpr int ASZ  = 128 * ASTR;
    constexpr int BSZ  = 64 * BSTR;
    constexpr int SET  = 2 * (ASZ + BSZ);        // {Ahi,Alo,Bhi,Blo}
    constexpr int NT   = NP / 16;                // n8-tiles per warp

    extern __shared__ char smraw[];
    uint32_t raw = smem_u32(smraw);
    uint32_t sb  = (raw + 255) & ~255u;
    char* base   = smraw + (sb - raw);

    const int tid = threadIdx.x, wid = tid >> 5, lane = tid & 31;
    const int g = lane >> 2, tg = lane & 3;
    const int half = blockIdx.y;
    const int m0   = blockIdx.x * 128;
    const int z    = blockIdx.z;
    const float* __restrict__ W    = half ? Wn : Wx;
    const float* __restrict__ bias = half ? bn : bx;

    // row pointers
    const float** rowp = (const float**)(base + 2 * SET);
    if (MODE == 0) {
        if (half == 0) {
            if (tid < 128) rowp[tid] = xsrc + (size_t)__ldg(&xids[m0 + tid]) * DIM;
        } else {
            for (int i = tid; i < 1280; i += 256)
                rowp[i] = msrc + (size_t)__ldg(&mids[(size_t)m0 * 10 + i]) * DIM;
        }
    } else if (MODE == 1) {
        if (tid < 128) rowp[tid] = half ? (msrc + (size_t)(m0 + tid) * DIM)
                                        : (xsrc + (size_t)__ldg(&xids[m0 + tid]) * DIM);
    } else {
        if (tid < 128) rowp[tid] = (half ? msrc : xsrc) + (size_t)(m0 + tid) * DIM;
    }
    __syncthreads();

    // loader thread mapping
    const int ar  = tid >> 1;               // A row 0..127
    const int akq = (tid & 1) * 32;         // A k offset (floats)
    const int bkl = tid >> 2;               // B k row 0..63
    const int bn0 = (tid & 3) * (NP / 4);   // B n offset
    constexpr int QB = NP / 16;             // float4s per thread for B

    auto load_chunk = [&](int c, int s) {
        char* Ah = base + s * SET;
        char* Al = Ah + ASZ;
        char* Bh = Al + ASZ;
        char* Bl = Bh + BSZ;
        float4 v[8];
        if (MODE == 0 && half == 1) {        // fused mean-of-10 gather
#pragma unroll
            for (int q = 0; q < 8; ++q) v[q] = make_float4(0.f, 0.f, 0.f, 0.f);
            for (int j = 0; j < 10; ++j) {
                const float4* p = (const float4*)(rowp[ar * 10 + j] + c * 64 + akq);
#pragma unroll
                for (int q = 0; q < 8; ++q) {
                    float4 t = __ldg(p + q);
                    v[q].x += t.x; v[q].y += t.y; v[q].z += t.z; v[q].w += t.w;
                }
            }
#pragma unroll
            for (int q = 0; q < 8; ++q) {
                v[q].x *= 0.1f; v[q].y *= 0.1f; v[q].z *= 0.1f; v[q].w *= 0.1f;
            }
        } else {
            const float4* p = (const float4*)(rowp[ar] + c * 64 + akq);
#pragma unroll
            for (int q = 0; q < 8; ++q) v[q] = __ldg(p + q);
        }
#pragma unroll
        for (int q = 0; q < 8; ++q) {
            uint32_t o = (uint32_t)ar * ASTR + (uint32_t)(akq + q * 4) * 2;
            split_store(Ah + o, Al + o, v[q]);
        }
        const float4* wp = (const float4*)(W + (size_t)(c * 64 + bkl) * HIDV + z * NP + bn0);
#pragma unroll
        for (int q = 0; q < QB; ++q) {
            float4 t = __ldg(wp + q);
            uint32_t o = (uint32_t)bkl * BSTR + (uint32_t)(bn0 + q * 4) * 2;
            split_store(Bh + o, Bl + o, t);
        }
    };

    // mma state
    const int wm  = (wid & 3) * 32;
    const int wnl = (wid >> 2) * (NP / 2);
    float acc[2][NT][4];
#pragma unroll
    for (int mt = 0; mt < 2; ++mt)
#pragma unroll
        for (int nt = 0; nt < NT; ++nt)
#pragma unroll
            for (int i = 0; i < 4; ++i) acc[mt][nt][i] = 0.f;

    auto mma_chunk = [&](int s) {
        uint32_t Ahb = sb + s * SET;
        uint32_t Bhb = Ahb + 2 * ASZ;
#pragma unroll
        for (int ks = 0; ks < 4; ++ks) {
            const int k0 = ks * 16;
            uint32_t ah[2][4], al[2][4];
#pragma unroll
            for (int mt = 0; mt < 2; ++mt) {
                uint32_t ra = Ahb + (uint32_t)(wm + mt * 16 + (lane & 15)) * ASTR
                            + (uint32_t)(lane >> 4) * 16 + (uint32_t)k0 * 2;
                ldsm4(ah[mt], ra);
                ldsm4(al[mt], ra + ASZ);
            }
            uint32_t bhf[NT][2], blf[NT][2];
#pragma unroll
            for (int nt = 0; nt < NT; ++nt) {
                uint32_t rb = Bhb + (uint32_t)(k0 + (lane & 15)) * BSTR
                            + (uint32_t)(wnl + nt * 8) * 2;
                ldsm2t(bhf[nt], rb);
                ldsm2t(blf[nt], rb + BSZ);
            }
#pragma unroll
            for (int nt = 0; nt < NT; ++nt)
#pragma unroll
                for (int mt = 0; mt < 2; ++mt) mma16816(acc[mt][nt], ah[mt], bhf[nt]);
#pragma unroll
            for (int nt = 0; nt < NT; ++nt)
#pragma unroll
                for (int mt = 0; mt < 2; ++mt) mma16816(acc[mt][nt], ah[mt], blf[nt]);
#pragma unroll
            for (int nt = 0; nt < NT; ++nt)
#pragma unroll
                for (int mt = 0; mt < 2; ++mt) mma16816(acc[mt][nt], al[mt], bhf[nt]);
        }
    };

    // mainloop: 4 K-chunks of 64, double-buffered (mma first, then prefetch)
    load_chunk(0, 0);
    __syncthreads();
#pragma unroll 1
    for (int c = 0; c < 4; ++c) {
        mma_chunk(c & 1);
        if (c < 3) load_chunk(c + 1, (c + 1) & 1);
        __syncthreads();
    }

    // epilogue
    if (MODE == 0) {
        // relu + group-25 column mean into outp (= mh1), via SMEM staging
        float* ep = (float*)base;   // 128 x 130 fp32, aliases tile buffers
#pragma unroll
        for (int mt = 0; mt < 2; ++mt)
#pragma unroll
            for (int nt = 0; nt < NT; ++nt) {
                int c0 = wnl + nt * 8 + 2 * tg;
                float2 bv = *(const float2*)(bias + c0);
                int r0 = wm + mt * 16 + g;
                ep[r0 * 130 + c0]           = fmaxf(acc[mt][nt][0] + bv.x, 0.f);
                ep[r0 * 130 + c0 + 1]       = fmaxf(acc[mt][nt][1] + bv.y, 0.f);
                ep[(r0 + 8) * 130 + c0]     = fmaxf(acc[mt][nt][2] + bv.x, 0.f);
                ep[(r0 + 8) * 130 + c0 + 1] = fmaxf(acc[mt][nt][3] + bv.y, 0.f);
            }
        __syncthreads();
        const int gbase = m0 / 25;
        for (int idx = tid; idx < 7 * 128; idx += 256) {
            int gi = idx >> 7, col = idx & 127;
            int gg = gbase + gi;
            int rs = gg * 25 - m0;      if (rs < 0)   rs = 0;
            int re = gg * 25 + 25 - m0; if (re > 128) re = 128;
            if (rs < re) {
                float s = 0.f;
                for (int r = rs; r < re; ++r) s += ep[r * 130 + col];
                atomicAdd(&outp[(size_t)gg * DIM + half * HIDV + col], s * (1.f / 25.f));
            }
        }
    } else {
#pragma unroll
        for (int mt = 0; mt < 2; ++mt)
#pragma unroll
            for (int nt = 0; nt < NT; ++nt) {
                int cg = z * NP + wnl + nt * 8 + 2 * tg;
                float2 bv = *(const float2*)(bias + cg);
                int r0 = m0 + wm + mt * 16 + g;
                float2 o0 = make_float2(acc[mt][nt][0] + bv.x, acc[mt][nt][1] + bv.y);
                float2 o1 = make_float2(acc[mt][nt][2] + bv.x, acc[mt][nt][3] + bv.y);
                if (MODE == 1) {
                    o0.x = fmaxf(o0.x, 0.f); o0.y = fmaxf(o0.y, 0.f);
                    o1.x = fmaxf(o1.x, 0.f); o1.y = fmaxf(o1.y, 0.f);
                }
                *(float2*)&outp[(size_t)r0 * DIM + half * HIDV + cg]       = o0;
                *(float2*)&outp[(size_t)(r0 + 8) * DIM + half * HIDV + cg] = o1;
            }
    }
}

// smem sizes (host mirrors of kernel constants)
#define SM_L1 (2 * (2 * (128 * 144 + 64 * 272)) + 10240 + 256)   // 153856
#define SM_SG (2 * (2 * (128 * 144 + 64 * 80))  + 1024  + 256)   // 95488

// ---------------------------------------------------------------------------
// Gather/mean for m1: one warp per output row.
// ---------------------------------------------------------------------------
template <int K>
__global__ __launch_bounds__(256)
void mean_kernel(const float* __restrict__ src, const int* __restrict__ ids,
                 float* __restrict__ out, int rows, float inv)
{
    int warp = (blockIdx.x * (blockDim.x >> 5)) + (threadIdx.x >> 5);
    if (warp >= rows) return;
    int lane = threadIdx.x & 31;

    float4 a0 = make_float4(0.f, 0.f, 0.f, 0.f);
    float4 a1 = a0;
#pragma unroll
    for (int j = 0; j < K; ++j) {
        long r = (long)__ldg(&ids[(long)warp * K + j]);
        const float4* rp = reinterpret_cast<const float4*>(src + r * DIM);
        float4 v0 = __ldg(rp + lane);
        float4 v1 = __ldg(rp + lane + 32);
        a0.x += v0.x; a0.y += v0.y; a0.z += v0.z; a0.w += v0.w;
        a1.x += v1.x; a1.y += v1.y; a1.z += v1.z; a1.w += v1.w;
    }
    a0.x *= inv; a0.y *= inv; a0.z *= inv; a0.w *= inv;
    a1.x *= inv; a1.y *= inv; a1.z *= inv; a1.w *= inv;
    float4* op = reinterpret_cast<float4*>(out + (long)warp * DIM);
    op[lane]      = a0;
    op[lane + 32] = a1;
}

// ---------------------------------------------------------------------------
// Final: row-normalize g0 then tiny FC [256 -> 7].
// ---------------------------------------------------------------------------
__global__ __launch_bounds__(256)
void final_kernel(const float* __restrict__ g0, const float* __restrict__ Wfc,
                  const float* __restrict__ bfc, float* __restrict__ out)
{
    const int row = blockIdx.x;
    __shared__ float s[DIM];
    __shared__ float red[8];
    __shared__ float s_inv;
    const int t = threadIdx.x;

    float v = g0[(long)row * DIM + t];
    s[t] = v;
    float sq = v * v;
#pragma unroll
    for (int o = 16; o; o >>= 1) sq += __shfl_xor_sync(0xFFFFFFFFu, sq, o);
    if ((t & 31) == 0) red[t >> 5] = sq;
    __syncthreads();
    if (t == 0) {
        float tot = 0.f;
#pragma unroll
        for (int i = 0; i < 8; ++i) tot += red[i];
        s_inv = 1.f / fmaxf(sqrtf(tot), 1e-12f);
    }
    __syncthreads();
    const float inv = s_inv;

    const int w = t >> 5, l = t & 31;
    if (w < 7) {
        float acc = 0.f;
#pragma unroll
        for (int k = l; k < DIM; k += 32)
            acc = fmaf(s[k], __ldg(&Wfc[k * 7 + w]), acc);
#pragma unroll
        for (int o = 16; o; o >>= 1) acc += __shfl_xor_sync(0xFFFFFFFFu, acc, o);
        if (l == 0) out[row * 7 + w] = acc * inv + bfc[w];
    }
}

// ---------------------------------------------------------------------------
extern "C" void kernel_launch(void* const* d_in, const int* in_sizes, int n_in,
                              void* d_out, int out_size)
{
    const int*   ids   = (const int*)  d_in[0];
    const int*   ids1  = (const int*)  d_in[1];
    const int*   ids2  = (const int*)  d_in[2];
    const float* feats = (const float*)d_in[3];
    const float* Wx1   = (const float*)d_in[4];
    const float* bx1   = (const float*)d_in[5];
    const float* Wn1   = (const float*)d_in[6];
    const float* bn1   = (const float*)d_in[7];
    const float* Wx2   = (const float*)d_in[8];
    const float* bx2   = (const float*)d_in[9];
    const float* Wn2   = (const float*)d_in[10];
    const float* bn2   = (const float*)d_in[11];
    const float* Wfc   = (const float*)d_in[12];
    const float* bfc   = (const float*)d_in[13];
    float* out = (float*)d_out;

    float *m1, *mh1, *h0, *g0;
    cudaGetSymbolAddress((void**)&m1,  g_m1);
    cudaGetSymbolAddress((void**)&mh1, g_mh1);
    cudaGetSymbolAddress((void**)&h0,  g_h0);
    cudaGetSymbolAddress((void**)&g0,  g_g0);

    cudaFuncSetAttribute(gemm_k<0, 128>, cudaFuncAttributeMaxDynamicSharedMemorySize, SM_L1);
    cudaFuncSetAttribute(gemm_k<1, 32>,  cudaFuncAttributeMaxDynamicSharedMemorySize, SM_SG);
    cudaFuncSetAttribute(gemm_k<2, 32>,  cudaFuncAttributeMaxDynamicSharedMemorySize, SM_SG);

    // 1) mh1 = 0 (accumulated by fused GEMM epilogue)
    cudaMemsetAsync(mh1, 0, (size_t)NB * DIM * sizeof(float));
    // 2) m1 = mean_25(feats[ids1])
    mean_kernel<S0V><<<(NB * 32 + 255) / 256, 256>>>(feats, ids1, m1, NB, 1.f / S0V);
    // 3) fused l1: [f1@Wx1 ; mean10(f2)@Wn1] -> relu -> group-25 mean -> mh1
    gemm_k<0, 128><<<dim3(M1ROWS / 128, 2, 1), 256, SM_L1>>>(
        feats, ids1, feats, ids2, Wx1, bx1, Wn1, bn1, mh1);
    // 4) h0 = relu([f0@Wx1 ; m1@Wn1])
    gemm_k<1, 32><<<dim3(NB / 128, 2, 4), 256, SM_SG>>>(
        feats, ids, m1, nullptr, Wx1, bx1, Wn1, bn1, h0);
    // 5) g0 = [h0@Wx2 ; mh1@Wn2]
    gemm_k<2, 32><<<dim3(NB / 128, 2, 4), 256, SM_SG>>>(
        h0, nullptr, mh1, nullptr, Wx2, bx2, Wn2, bn2, g0);
    // 6) out = normalize(g0) @ Wfc + bfc
    final_kernel<<<NB, 256>>>(g0, Wfc, bfc, out);
}

// round 7
// speedup vs baseline: 1.5681x; 1.4939x over previous
#include <cuda_runtime.h>
#include <cuda_bf16.h>
#include <cstdint>

// ---------------------------------------------------------------------------
// GraphSAGE 2-layer mean-aggregator forward.
//   m2h/m2l = bf16 hi/lo split of mean_10(feats[ids2])          [12800,256]
//   m1  = mean_25(feats[ids1])                                  [512,256]
//   mh1 = mean_25(relu([f1@Wx1+bx1 ; m2@Wn1+bn1]))  (h1 never stored)
//   h0  = [f0@Wx1+bx1 ; m1@Wn1+bn1]        (stored PRE-relu; relu on read)
//   g0  = [relu(h0)@Wx2+bx2 ; mh1@Wn2+bn2]
//   out = (g0 / max(||g0||,1e-12)) @ Wfc + bfc
// ---------------------------------------------------------------------------

#define NB     512
#define S0V    25
#define DIM    256
#define HIDV   128
#define M1ROWS (NB * S0V)   // 12800

__device__ __align__(16) __nv_bfloat16 g_m2h[M1ROWS * DIM];  // 6.55 MB
__device__ __align__(16) __nv_bfloat16 g_m2l[M1ROWS * DIM];  // 6.55 MB
__device__ float g_m1 [NB * DIM];
__device__ float g_mh1[NB * DIM];
__device__ float g_h0 [NB * DIM];
__device__ float g_g0 [NB * DIM];

// ---------------------------------------------------------------------------
// helpers
// ---------------------------------------------------------------------------
__device__ __forceinline__ uint32_t smem_u32(const void* p) {
    uint32_t a;
    asm("{ .reg .u64 t; cvta.to.shared.u64 t, %1; cvt.u32.u64 %0, t; }" : "=r"(a) : "l"(p));
    return a;
}
__device__ __forceinline__ uint32_t packbf(__nv_bfloat16 a, __nv_bfloat16 b) {
    __nv_bfloat162 t(a, b);
    return *reinterpret_cast<uint32_t*>(&t);
}
// split float4 into bf16 hi + bf16 residual, 8B store each
__device__ __forceinline__ void split_store(void* ph, void* pl, float4 v) {
    __nv_bfloat16 hx = __float2bfloat16_rn(v.x);
    __nv_bfloat16 hy = __float2bfloat16_rn(v.y);
    __nv_bfloat16 hz = __float2bfloat16_rn(v.z);
    __nv_bfloat16 hw = __float2bfloat16_rn(v.w);
    __nv_bfloat16 lx = __float2bfloat16_rn(v.x - __bfloat162float(hx));
    __nv_bfloat16 ly = __float2bfloat16_rn(v.y - __bfloat162float(hy));
    __nv_bfloat16 lz = __float2bfloat16_rn(v.z - __bfloat162float(hz));
    __nv_bfloat16 lw = __float2bfloat16_rn(v.w - __bfloat162float(hw));
    *reinterpret_cast<uint2*>(ph) = make_uint2(packbf(hx, hy), packbf(hz, hw));
    *reinterpret_cast<uint2*>(pl) = make_uint2(packbf(lx, ly), packbf(lz, lw));
}
__device__ __forceinline__ void ldsm4(uint32_t* r, uint32_t addr) {
    asm volatile("ldmatrix.sync.aligned.m8n8.x4.shared.b16 {%0,%1,%2,%3}, [%4];"
        : "=r"(r[0]), "=r"(r[1]), "=r"(r[2]), "=r"(r[3]) : "r"(addr));
}
__device__ __forceinline__ void ldsm2t(uint32_t* r, uint32_t addr) {
    asm volatile("ldmatrix.sync.aligned.m8n8.x2.trans.shared.b16 {%0,%1}, [%2];"
        : "=r"(r[0]), "=r"(r[1]) : "r"(addr));
}
__device__ __forceinline__ void mma16816(float* d, const uint32_t* a, const uint32_t* b) {
    asm volatile("mma.sync.aligned.m16n8k16.row.col.f32.bf16.bf16.f32 "
        "{%0,%1,%2,%3},{%4,%5,%6,%7},{%8,%9},{%0,%1,%2,%3};"
        : "+f"(d[0]), "+f"(d[1]), "+f"(d[2]), "+f"(d[3])
        : "r"(a[0]), "r"(a[1]), "r"(a[2]), "r"(a[3]), "r"(b[0]), "r"(b[1]));
}

// ---------------------------------------------------------------------------
// m2 gather: mean of 10 random feat rows -> bf16 hi/lo split. One warp/row,
// 12800 warps (86/SM) for full memory-level parallelism on the 131 MB gather.
// ---------------------------------------------------------------------------
__global__ __launch_bounds__(256)
void m2_gather(const float* __restrict__ feats, const int* __restrict__ ids2,
               __nv_bfloat16* __restrict__ hi, __nv_bfloat16* __restrict__ lo)
{
    int warp = blockIdx.x * 8 + (threadIdx.x >> 5);
    if (warp >= M1ROWS) return;
    int lane = threadIdx.x & 31;

    float4 a0 = make_float4(0.f, 0.f, 0.f, 0.f);
    float4 a1 = a0;
    const int* bp = ids2 + (size_t)warp * 10;
#pragma unroll
    for (int j = 0; j < 10; ++j) {
        const float4* rp = reinterpret_cast<const float4*>(feats + (size_t)__ldg(&bp[j]) * DIM);
        float4 v0 = __ldg(rp + lane);
        float4 v1 = __ldg(rp + lane + 32);
        a0.x += v0.x; a0.y += v0.y; a0.z += v0.z; a0.w += v0.w;
        a1.x += v1.x; a1.y += v1.y; a1.z += v1.z; a1.w += v1.w;
    }
    a0.x *= 0.1f; a0.y *= 0.1f; a0.z *= 0.1f; a0.w *= 0.1f;
    a1.x *= 0.1f; a1.y *= 0.1f; a1.z *= 0.1f; a1.w *= 0.1f;

    size_t o0 = (size_t)warp * DIM + lane * 4;
    split_store(hi + o0,       lo + o0,       a0);
    split_store(hi + o0 + 128, lo + o0 + 128, a1);
}

// ---------------------------------------------------------------------------
// m1 mean: one block per output row, fully coalesced.
// ---------------------------------------------------------------------------
__global__ __launch_bounds__(256)
void m1_mean(const float* __restrict__ feats, const int* __restrict__ ids1,
             float* __restrict__ m1)
{
    const int row = blockIdx.x, t = threadIdx.x;
    const int* bp = ids1 + (size_t)row * S0V;
    float acc = 0.f;
#pragma unroll
    for (int j = 0; j < S0V; ++j)
        acc += __ldg(&feats[(size_t)__ldg(&bp[j]) * DIM + t]);
    m1[(size_t)row * DIM + t] = acc * (1.f / S0V);
}

// ---------------------------------------------------------------------------
// Layer-1 GEMM: A[128,256] @ W[256,128] (+bias) -> relu -> group-25 mean ->
// atomicAdd(mh1). half 0: A = feats[ids1] (fp32 gather + split); half 1:
// A = pre-split bf16 (g_m2h/g_m2l) — no gather, no convert.
// bf16 hi/lo 3-split: D = Ah*Bh + Ah*Bl + Al*Bh (fp32 accum).
// ---------------------------------------------------------------------------
#define ASTR 144
#define BSTR 272
#define ASZ  (128 * ASTR)
#define BSZ  (64 * BSTR)
#define SETB (2 * (ASZ + BSZ))        // 71680
#define SM_L1 (2 * SETB + 1024 + 256) // 144640

__global__ __launch_bounds__(256, 1)
void l1_gemm(const float* __restrict__ feats, const int* __restrict__ ids1,
             const __nv_bfloat16* __restrict__ m2h, const __nv_bfloat16* __restrict__ m2l,
             const float* __restrict__ Wx, const float* __restrict__ bx,
             const float* __restrict__ Wn, const float* __restrict__ bn,
             float* __restrict__ mh1)
{
    extern __shared__ char smraw[];
    uint32_t raw = smem_u32(smraw);
    uint32_t sb  = (raw + 255) & ~255u;
    char* base   = smraw + (sb - raw);

    const int tid = threadIdx.x, wid = tid >> 5, lane = tid & 31;
    const int g = lane >> 2, tg = lane & 3;
    const int half = blockIdx.y;
    const int m0   = blockIdx.x * 128;
    const float* __restrict__ W    = half ? Wn : Wx;
    const float* __restrict__ bias = half ? bn : bx;

    const float** rowp = (const float**)(base + 2 * SETB);
    if (half == 0 && tid < 128)
        rowp[tid] = feats + (size_t)__ldg(&ids1[m0 + tid]) * DIM;
    __syncthreads();

    const int ar  = tid >> 1;             // A row 0..127
    const int akq = (tid & 1) * 32;       // A col offset (elems)
    const int bkl = tid >> 2;             // B k row 0..63
    const int bn0 = (tid & 3) * 32;       // B n offset

    auto load_chunk = [&](int c, int s) {
        char* Ah = base + s * SETB;
        char* Al = Ah + ASZ;
        char* Bh = Al + ASZ;
        char* Bl = Bh + BSZ;
        if (half == 0) {
            const float4* p = (const float4*)(rowp[ar] + c * 64 + akq);
#pragma unroll
            for (int q = 0; q < 8; ++q) {
                float4 v = __ldg(p + q);
                uint32_t o = (uint32_t)ar * ASTR + (uint32_t)(akq + q * 4) * 2;
                split_store(Ah + o, Al + o, v);
            }
        } else {
            const uint4* hp = (const uint4*)(m2h + (size_t)(m0 + ar) * DIM + c * 64 + akq);
            const uint4* lp = (const uint4*)(m2l + (size_t)(m0 + ar) * DIM + c * 64 + akq);
#pragma unroll
            for (int q = 0; q < 4; ++q) {
                uint32_t o = (uint32_t)ar * ASTR + (uint32_t)(akq + q * 8) * 2;
                *reinterpret_cast<uint4*>(Ah + o) = __ldg(hp + q);
                *reinterpret_cast<uint4*>(Al + o) = __ldg(lp + q);
            }
        }
        const float4* wp = (const float4*)(W + (size_t)(c * 64 + bkl) * HIDV + bn0);
#pragma unroll
        for (int q = 0; q < 8; ++q) {
            float4 t = __ldg(wp + q);
            uint32_t o = (uint32_t)bkl * BSTR + (uint32_t)(bn0 + q * 4) * 2;
            split_store(Bh + o, Bl + o, t);
        }
    };

    const int wm  = (wid & 3) * 32;
    const int wnl = (wid >> 2) * 64;
    float acc[2][8][4];
#pragma unroll
    for (int mt = 0; mt < 2; ++mt)
#pragma unroll
        for (int nt = 0; nt < 8; ++nt)
#pragma unroll
            for (int i = 0; i < 4; ++i) acc[mt][nt][i] = 0.f;

    auto mma_chunk = [&](int s) {
        uint32_t Ab = sb + s * SETB;
        uint32_t Bb = Ab + 2 * ASZ;
#pragma unroll
        for (int ks = 0; ks < 4; ++ks) {
            const int k0 = ks * 16;
            uint32_t ah[2][4], al[2][4];
#pragma unroll
            for (int mt = 0; mt < 2; ++mt) {
                uint32_t ra = Ab + (uint32_t)(wm + mt * 16 + (lane & 15)) * ASTR
                            + (uint32_t)(lane >> 4) * 16 + (uint32_t)k0 * 2;
                ldsm4(ah[mt], ra);
                ldsm4(al[mt], ra + ASZ);
            }
            uint32_t bhf[8][2], blf[8][2];
#pragma unroll
            for (int nt = 0; nt < 8; ++nt) {
                uint32_t rb = Bb + (uint32_t)(k0 + (lane & 15)) * BSTR
                            + (uint32_t)(wnl + nt * 8) * 2;
                ldsm2t(bhf[nt], rb);
                ldsm2t(blf[nt], rb + BSZ);
            }
#pragma unroll
            for (int nt = 0; nt < 8; ++nt)
#pragma unroll
                for (int mt = 0; mt < 2; ++mt) mma16816(acc[mt][nt], ah[mt], bhf[nt]);
#pragma unroll
            for (int nt = 0; nt < 8; ++nt)
#pragma unroll
                for (int mt = 0; mt < 2; ++mt) mma16816(acc[mt][nt], ah[mt], blf[nt]);
#pragma unroll
            for (int nt = 0; nt < 8; ++nt)
#pragma unroll
                for (int mt = 0; mt < 2; ++mt) mma16816(acc[mt][nt], al[mt], bhf[nt]);
        }
    };

    load_chunk(0, 0);
    __syncthreads();
#pragma unroll 1
    for (int c = 0; c < 4; ++c) {
        mma_chunk(c & 1);
        if (c < 3) load_chunk(c + 1, (c + 1) & 1);
        __syncthreads();
    }

    // epilogue: +bias -> relu -> SMEM stage -> group-25 column mean -> atomics
    float* ep = (float*)base;   // 128 x 130 fp32 (66560 B, fits in set0)
#pragma unroll
    for (int mt = 0; mt < 2; ++mt)
#pragma unroll
        for (int nt = 0; nt < 8; ++nt) {
            int c0 = wnl + nt * 8 + 2 * tg;
            float2 bv = *(const float2*)(bias + c0);
            int r0 = wm + mt * 16 + g;
            ep[r0 * 130 + c0]           = fmaxf(acc[mt][nt][0] + bv.x, 0.f);
            ep[r0 * 130 + c0 + 1]       = fmaxf(acc[mt][nt][1] + bv.y, 0.f);
            ep[(r0 + 8) * 130 + c0]     = fmaxf(acc[mt][nt][2] + bv.x, 0.f);
            ep[(r0 + 8) * 130 + c0 + 1] = fmaxf(acc[mt][nt][3] + bv.y, 0.f);
        }
    __syncthreads();
    const int gbase = m0 / 25;
    for (int idx = tid; idx < 7 * 128; idx += 256) {
        int gi = idx >> 7, col = idx & 127;
        int gg = gbase + gi;
        int rs = gg * 25 - m0;      if (rs < 0)   rs = 0;
        int re = gg * 25 + 25 - m0; if (re > 128) re = 128;
        if (rs < re) {
            float s = 0.f;
            for (int r = rs; r < re; ++r) s += ep[r * 130 + col];
            atomicAdd(&mh1[(size_t)gg * DIM + half * HIDV + col], s * (1.f / 25.f));
        }
    }
}

// ---------------------------------------------------------------------------
// Small GEMM, split-K for parallelism: grid (8 M-tiles of 64, 2 halves,
// 4 K-splits of 64) = 64 blocks, one K-chunk each, fp32 atomicAdd epilogue.
// Bias added only by the kz==0 split. MODE 1 (h0): A half0 = feats[ids]
// gather, half1 = m1; output stored PRE-relu. MODE 2 (g0): A half0 =
// relu(h0) on load, half1 = mh1.
// ---------------------------------------------------------------------------
#define SASZ (64 * ASTR)
#define SM_SK (2 * SASZ + 2 * BSZ + 256)   // 53504

template <int MODE>
__global__ __launch_bounds__(256)
void sgemm_k(const float* __restrict__ xsrc, const int* __restrict__ xids,
             const float* __restrict__ msrc,
             const float* __restrict__ Wx, const float* __restrict__ bx,
             const float* __restrict__ Wn, const float* __restrict__ bn,
             float* __restrict__ outp)
{
    extern __shared__ char smraw[];
    uint32_t raw = smem_u32(smraw);
    uint32_t sb  = (raw + 255) & ~255u;
    char* base   = smraw + (sb - raw);
    char* Ah = base;
    char* Al = Ah + SASZ;
    char* Bh = Al + SASZ;
    char* Bl = Bh + BSZ;

    const int tid = threadIdx.x, wid = tid >> 5, lane = tid & 31;
    const int g = lane >> 2, tg = lane & 3;
    const int m0 = blockIdx.x * 64;
    const int half = blockIdx.y;
    const int kz   = blockIdx.z;
    const float* __restrict__ W    = half ? Wn : Wx;
    const float* __restrict__ bias = half ? bn : bx;

    // load A chunk [64 rows x 64 k]
    {
        const int ar = tid >> 2, akq = (tid & 3) * 16;
        const float* src;
        if (half)              src = msrc + (size_t)(m0 + ar) * DIM;
        else if (MODE == 1)    src = xsrc + (size_t)__ldg(&xids[m0 + ar]) * DIM;
        else                   src = xsrc + (size_t)(m0 + ar) * DIM;
        const float4* p = (const float4*)(src + kz * 64 + akq);
#pragma unroll
        for (int q = 0; q < 4; ++q) {
            float4 v = __ldg(p + q);
            if (MODE == 2 && half == 0) {
                v.x = fmaxf(v.x, 0.f); v.y = fmaxf(v.y, 0.f);
                v.z = fmaxf(v.z, 0.f); v.w = fmaxf(v.w, 0.f);
            }
            uint32_t o = (uint32_t)ar * ASTR + (uint32_t)(akq + q * 4) * 2;
            split_store(Ah + o, Al + o, v);
        }
    }
    // load B chunk [64 k x 128 n]
    {
        const int bkl = tid >> 2, bn0 = (tid & 3) * 32;
        const float4* wp = (const float4*)(W + (size_t)(kz * 64 + bkl) * HIDV + bn0);
#pragma unroll
        for (int q = 0; q < 8; ++q) {
            float4 t = __ldg(wp + q);
            uint32_t o = (uint32_t)bkl * BSTR + (uint32_t)(bn0 + q * 4) * 2;
            split_store(Bh + o, Bl + o, t);
        }
    }
    __syncthreads();

    const int wm  = (wid & 3) * 16;
    const int wnl = (wid >> 2) * 64;
    float acc[8][4];
#pragma unroll
    for (int nt = 0; nt < 8; ++nt)
#pragma unroll
        for (int i = 0; i < 4; ++i) acc[nt][i] = 0.f;

    const uint32_t Ab = sb, Bb = sb + 2 * SASZ;
#pragma unroll
    for (int ks = 0; ks < 4; ++ks) {
        const int k0 = ks * 16;
        uint32_t ah[4], al[4];
        uint32_t ra = Ab + (uint32_t)(wm + (lane & 15)) * ASTR
                    + (uint32_t)(lane >> 4) * 16 + (uint32_t)k0 * 2;
        ldsm4(ah, ra);
        ldsm4(al, ra + SASZ);
        uint32_t bhf[8][2], blf[8][2];
#pragma unroll
        for (int nt = 0; nt < 8; ++nt) {
            uint32_t rb = Bb + (uint32_t)(k0 + (lane & 15)) * BSTR
                        + (uint32_t)(wnl + nt * 8) * 2;
            ldsm2t(bhf[nt], rb);
            ldsm2t(blf[nt], rb + BSZ);
        }
#pragma unroll
        for (int nt = 0; nt < 8; ++nt) mma16816(acc[nt], ah, bhf[nt]);
#pragma unroll
        for (int nt = 0; nt < 8; ++nt) mma16816(acc[nt], ah, blf[nt]);
#pragma unroll
        for (int nt = 0; nt < 8; ++nt) mma16816(acc[nt], al, bhf[nt]);
    }

    // epilogue: atomic accumulate (bias only from kz==0)
#pragma unroll
    for (int nt = 0; nt < 8; ++nt) {
        int c0 = wnl + nt * 8 + 2 * tg;
        float bvx = 0.f, bvy = 0.f;
        if (kz == 0) { float2 bv = *(const float2*)(bias + c0); bvx = bv.x; bvy = bv.y; }
        int r0 = m0 + wm + g;
        float* d0 = &outp[(size_t)r0 * DIM + half * HIDV + c0];
        atomicAdd(d0,     acc[nt][0] + bvx);
        atomicAdd(d0 + 1, acc[nt][1] + bvy);
        float* d1 = &outp[(size_t)(r0 + 8) * DIM + half * HIDV + c0];
        atomicAdd(d1,     acc[nt][2] + bvx);
        atomicAdd(d1 + 1, acc[nt][3] + bvy);
    }
}

// ---------------------------------------------------------------------------
// Final: row-normalize g0 then tiny FC [256 -> 7].
// ---------------------------------------------------------------------------
__global__ __launch_bounds__(256)
void final_kernel(const float* __restrict__ g0, const float* __restrict__ Wfc,
                  const float* __restrict__ bfc, float* __restrict__ out)
{
    const int row = blockIdx.x;
    __shared__ float s[DIM];
    __shared__ float red[8];
    __shared__ float s_inv;
    const int t = threadIdx.x;

    float v = g0[(size_t)row * DIM + t];
    s[t] = v;
    float sq = v * v;
#pragma unroll
    for (int o = 16; o; o >>= 1) sq += __shfl_xor_sync(0xFFFFFFFFu, sq, o);
    if ((t & 31) == 0) red[t >> 5] = sq;
    __syncthreads();
    if (t == 0) {
        float tot = 0.f;
#pragma unroll
        for (int i = 0; i < 8; ++i) tot += red[i];
        s_inv = 1.f / fmaxf(sqrtf(tot), 1e-12f);
    }
    __syncthreads();
    const float inv = s_inv;

    const int w = t >> 5, l = t & 31;
    if (w < 7) {
        float acc = 0.f;
#pragma unroll
        for (int k = l; k < DIM; k += 32)
            acc = fmaf(s[k], __ldg(&Wfc[k * 7 + w]), acc);
#pragma unroll
        for (int o = 16; o; o >>= 1) acc += __shfl_xor_sync(0xFFFFFFFFu, acc, o);
        if (l == 0) out[row * 7 + w] = acc * inv + bfc[w];
    }
}

// ---------------------------------------------------------------------------
extern "C" void kernel_launch(void* const* d_in, const int* in_sizes, int n_in,
                              void* d_out, int out_size)
{
    const int*   ids   = (const int*)  d_in[0];
    const int*   ids1  = (const int*)  d_in[1];
    const int*   ids2  = (const int*)  d_in[2];
    const float* feats = (const float*)d_in[3];
    const float* Wx1   = (const float*)d_in[4];
    const float* bx1   = (const float*)d_in[5];
    const float* Wn1   = (const float*)d_in[6];
    const float* bn1   = (const float*)d_in[7];
    const float* Wx2   = (const float*)d_in[8];
    const float* bx2   = (const float*)d_in[9];
    const float* Wn2   = (const float*)d_in[10];
    const float* bn2   = (const float*)d_in[11];
    const float* Wfc   = (const float*)d_in[12];
    const float* bfc   = (const float*)d_in[13];
    float* out = (float*)d_out;

    __nv_bfloat16 *m2h, *m2l;
    float *m1, *mh1, *h0, *g0;
    cudaGetSymbolAddress((void**)&m2h, g_m2h);
    cudaGetSymbolAddress((void**)&m2l, g_m2l);
    cudaGetSymbolAddress((void**)&m1,  g_m1);
    cudaGetSymbolAddress((void**)&mh1, g_mh1);
    cudaGetSymbolAddress((void**)&h0,  g_h0);
    cudaGetSymbolAddress((void**)&g0,  g_g0);

    cudaFuncSetAttribute(l1_gemm,   cudaFuncAttributeMaxDynamicSharedMemorySize, SM_L1);
    cudaFuncSetAttribute(sgemm_k<1>, cudaFuncAttributeMaxDynamicSharedMemorySize, SM_SK);
    cudaFuncSetAttribute(sgemm_k<2>, cudaFuncAttributeMaxDynamicSharedMemorySize, SM_SK);

    // zero accumulation targets
    cudaMemsetAsync(mh1, 0, (size_t)NB * DIM * sizeof(float));
    cudaMemsetAsync(h0,  0, (size_t)NB * DIM * sizeof(float));
    cudaMemsetAsync(g0,  0, (size_t)NB * DIM * sizeof(float));

    // 1) m2 gather + bf16 hi/lo split (high-occupancy, MLP-heavy)
    m2_gather<<<M1ROWS / 8, 256>>>(feats, ids2, m2h, m2l);
    // 2) m1 = mean_25(feats[ids1]) — coalesced block-per-row
    m1_mean<<<NB, 256>>>(feats, ids1, m1);
    // 3) l1 GEMM -> relu -> group-25 mean -> mh1 (h1 never materialized)
    l1_gemm<<<dim3(M1ROWS / 128, 2), 256, SM_L1>>>(
        feats, ids1, m2h, m2l, Wx1, bx1, Wn1, bn1, mh1);
    // 4) h0 (pre-relu) = [f0@Wx1+bx1 ; m1@Wn1+bn1], split-K
    sgemm_k<1><<<dim3(NB / 64, 2, 4), 256, SM_SK>>>(
        feats, ids, m1, Wx1, bx1, Wn1, bn1, h0);
    // 5) g0 = [relu(h0)@Wx2+bx2 ; mh1@Wn2+bn2], split-K
    sgemm_k<2><<<dim3(NB / 64, 2, 4), 256, SM_SK>>>(
        h0, nullptr, mh1, Wx2, bx2, Wn2, bn2, g0);
    // 6) out = normalize(g0) @ Wfc + bfc
    final_kernel<<<NB, 256>>>(g0, Wfc, bfc, out);
}

// round 8
// speedup vs baseline: 1.9917x; 1.2702x over previous
#include <cuda_runtime.h>
#include <cuda_bf16.h>
#include <cstdint>

// ---------------------------------------------------------------------------
// GraphSAGE 2-layer mean-aggregator forward.
// K1 (prep): m2 = mean10(feats[ids2]) -> bf16 hi/lo; f1/f0 gather-split;
//            m1 = mean25 -> split; W1/W2 split; zero accumulators.
// K2: l1 GEMM (relu + group-25 mean -> mh1, h1 never stored) + h0 GEMM.
// K3: g0 = [relu(h0)@Wx2+bx2 ; mh1@Wn2+bn2]  (split-K atomics)
// K4: out = normalize(g0) @ Wfc + bfc
// All GEMMs: bf16 hi/lo 3-split (Ah*Bh + Ah*Bl + Al*Bh), fp32 accum.
// ---------------------------------------------------------------------------

#define NB     512
#define DIM    256
#define HIDV   128
#define M1ROWS 12800

__device__ __align__(16) __nv_bfloat16 g_m2h[M1ROWS * DIM], g_m2l[M1ROWS * DIM];
__device__ __align__(16) __nv_bfloat16 g_f1h[M1ROWS * DIM], g_f1l[M1ROWS * DIM];
__device__ __align__(16) __nv_bfloat16 g_f0h[NB * DIM],     g_f0l[NB * DIM];
__device__ __align__(16) __nv_bfloat16 g_m1h[NB * DIM],     g_m1l[NB * DIM];
__device__ __align__(16) __nv_bfloat16 g_w1h[2 * DIM * HIDV], g_w1l[2 * DIM * HIDV];
__device__ __align__(16) __nv_bfloat16 g_w2h[2 * DIM * HIDV], g_w2l[2 * DIM * HIDV];
__device__ float g_acc[3 * NB * DIM];   // [0]=mh1, [1]=h0(pre-relu), [2]=g0

// ---------------------------------------------------------------------------
// helpers
// ---------------------------------------------------------------------------
__device__ __forceinline__ uint32_t smem_u32(const void* p) {
    uint32_t a;
    asm("{ .reg .u64 t; cvta.to.shared.u64 t, %1; cvt.u32.u64 %0, t; }" : "=r"(a) : "l"(p));
    return a;
}
__device__ __forceinline__ uint32_t packbf(__nv_bfloat16 a, __nv_bfloat16 b) {
    __nv_bfloat162 t(a, b);
    return *reinterpret_cast<uint32_t*>(&t);
}
__device__ __forceinline__ void split_store(void* ph, void* pl, float4 v) {
    __nv_bfloat16 hx = __float2bfloat16_rn(v.x);
    __nv_bfloat16 hy = __float2bfloat16_rn(v.y);
    __nv_bfloat16 hz = __float2bfloat16_rn(v.z);
    __nv_bfloat16 hw = __float2bfloat16_rn(v.w);
    __nv_bfloat16 lx = __float2bfloat16_rn(v.x - __bfloat162float(hx));
    __nv_bfloat16 ly = __float2bfloat16_rn(v.y - __bfloat162float(hy));
    __nv_bfloat16 lz = __float2bfloat16_rn(v.z - __bfloat162float(hz));
    __nv_bfloat16 lw = __float2bfloat16_rn(v.w - __bfloat162float(hw));
    *reinterpret_cast<uint2*>(ph) = make_uint2(packbf(hx, hy), packbf(hz, hw));
    *reinterpret_cast<uint2*>(pl) = make_uint2(packbf(lx, ly), packbf(lz, lw));
}
__device__ __forceinline__ void ldsm4(uint32_t* r, uint32_t addr) {
    asm volatile("ldmatrix.sync.aligned.m8n8.x4.shared.b16 {%0,%1,%2,%3}, [%4];"
        : "=r"(r[0]), "=r"(r[1]), "=r"(r[2]), "=r"(r[3]) : "r"(addr));
}
__device__ __forceinline__ void ldsm2t(uint32_t* r, uint32_t addr) {
    asm volatile("ldmatrix.sync.aligned.m8n8.x2.trans.shared.b16 {%0,%1}, [%2];"
        : "=r"(r[0]), "=r"(r[1]) : "r"(addr));
}
__device__ __forceinline__ void mma16816(float* d, const uint32_t* a, const uint32_t* b) {
    asm volatile("mma.sync.aligned.m16n8k16.row.col.f32.bf16.bf16.f32 "
        "{%0,%1,%2,%3},{%4,%5,%6,%7},{%8,%9},{%0,%1,%2,%3};"
        : "+f"(d[0]), "+f"(d[1]), "+f"(d[2]), "+f"(d[3])
        : "r"(a[0]), "r"(a[1]), "r"(a[2]), "r"(a[3]), "r"(b[0]), "r"(b[1]));
}

// ---------------------------------------------------------------------------
// K1: prep. Block roles by blockIdx.x:
//  [0,1600)    m2: warp/row mean-10 gather -> split
//  [1600,3200) f1: warp/row gather feats[ids1] -> split
//  [3200,3264) f0: warp/row gather feats[ids]  -> split
//  [3264,3328) m1: warp/row mean-25 gather -> split
//  [3328,3392) W split: Wx1,Wn1,Wx2,Wn2 -> g_w1h/l, g_w2h/l
//  [3392,3416) zero g_acc
// ---------------------------------------------------------------------------
__global__ __launch_bounds__(256)
void prep_kernel(const float* __restrict__ feats, const int* __restrict__ ids,
                 const int* __restrict__ ids1, const int* __restrict__ ids2,
                 const float* __restrict__ Wx1, const float* __restrict__ Wn1,
                 const float* __restrict__ Wx2, const float* __restrict__ Wn2)
{
    const int b = blockIdx.x, t = threadIdx.x, w = t >> 5, lane = t & 31;

    if (b < 1600) {                                  // m2 mean-10
        const int row = b * 8 + w;
        float4 a0 = make_float4(0.f, 0.f, 0.f, 0.f), a1 = a0;
        const int* bp = ids2 + (size_t)row * 10;
#pragma unroll
        for (int j = 0; j < 10; ++j) {
            const float4* rp = (const float4*)(feats + (size_t)__ldg(&bp[j]) * DIM);
            float4 v0 = __ldg(rp + lane), v1 = __ldg(rp + lane + 32);
            a0.x += v0.x; a0.y += v0.y; a0.z += v0.z; a0.w += v0.w;
            a1.x += v1.x; a1.y += v1.y; a1.z += v1.z; a1.w += v1.w;
        }
        a0.x *= 0.1f; a0.y *= 0.1f; a0.z *= 0.1f; a0.w *= 0.1f;
        a1.x *= 0.1f; a1.y *= 0.1f; a1.z *= 0.1f; a1.w *= 0.1f;
        size_t o = (size_t)row * DIM + lane * 4;
        split_store(g_m2h + o, g_m2l + o, a0);
        split_store(g_m2h + o + 128, g_m2l + o + 128, a1);
    } else if (b < 3200) {                           // f1 gather-split
        const int row = (b - 1600) * 8 + w;
        const float4* rp = (const float4*)(feats + (size_t)__ldg(&ids1[row]) * DIM);
        float4 v0 = __ldg(rp + lane), v1 = __ldg(rp + lane + 32);
        size_t o = (size_t)row * DIM + lane * 4;
        split_store(g_f1h + o, g_f1l + o, v0);
        split_store(g_f1h + o + 128, g_f1l + o + 128, v1);
    } else if (b < 3264) {                           // f0 gather-split
        const int row = (b - 3200) * 8 + w;
        const float4* rp = (const float4*)(feats + (size_t)__ldg(&ids[row]) * DIM);
        float4 v0 = __ldg(rp + lane), v1 = __ldg(rp + lane + 32);
        size_t o = (size_t)row * DIM + lane * 4;
        split_store(g_f0h + o, g_f0l + o, v0);
        split_store(g_f0h + o + 128, g_f0l + o + 128, v1);
    } else if (b < 3328) {                           // m1 mean-25
        const int row = (b - 3264) * 8 + w;
        float4 a0 = make_float4(0.f, 0.f, 0.f, 0.f), a1 = a0;
        const int* bp = ids1 + (size_t)row * 25;
#pragma unroll
        for (int j = 0; j < 25; ++j) {
            const float4* rp = (const float4*)(feats + (size_t)__ldg(&bp[j]) * DIM);
            float4 v0 = __ldg(rp + lane), v1 = __ldg(rp + lane + 32);
            a0.x += v0.x; a0.y += v0.y; a0.z += v0.z; a0.w += v0.w;
            a1.x += v1.x; a1.y += v1.y; a1.z += v1.z; a1.w += v1.w;
        }
        const float s = 1.f / 25.f;
        a0.x *= s; a0.y *= s; a0.z *= s; a0.w *= s;
        a1.x *= s; a1.y *= s; a1.z *= s; a1.w *= s;
        size_t o = (size_t)row * DIM + lane * 4;
        split_store(g_m1h + o, g_m1l + o, a0);
        split_store(g_m1h + o + 128, g_m1l + o + 128, a1);
    } else if (b < 3392) {                           // W split
        const int idx = (b - 3328) * 2048 + t * 8;
        const int mat = idx >> 15, off = idx & 32767;
        const float* src = (mat == 0) ? Wx1 : (mat == 1) ? Wn1 : (mat == 2) ? Wx2 : Wn2;
        __nv_bfloat16 *dh, *dl;
        if (mat < 2) { dh = g_w1h + mat * 32768 + off;       dl = g_w1l + mat * 32768 + off; }
        else         { dh = g_w2h + (mat - 2) * 32768 + off; dl = g_w2l + (mat - 2) * 32768 + off; }
        const float4* sp = (const float4*)(src + off);
        float4 v0 = __ldg(sp), v1 = __ldg(sp + 1);
        split_store(dh,     dl,     v0);
        split_store(dh + 4, dl + 4, v1);
    } else {                                         // zero g_acc
        const int basei = (b - 3392) * 16384 + t * 4;
        const float4 z = make_float4(0.f, 0.f, 0.f, 0.f);
#pragma unroll
        for (int q = 0; q < 16; ++q)
            *reinterpret_cast<float4*>(g_acc + basei + q * 1024) = z;
    }
}

// ---------------------------------------------------------------------------
// GEMM tile constants (M=64 tile, N=128, K-chunk=64; proven sgemm layout)
// ---------------------------------------------------------------------------
#define ASTR   144
#define BSTR   272
#define L1_ASZ (64 * ASTR)                   // 9216
#define L1_BSZ (64 * BSTR)                   // 17408
#define L1_SET (2 * (L1_ASZ + L1_BSZ))       // 53248
#define SM_K2  (2 * L1_SET + 256)            // 106752 (double buffer)
#define SM_K3  (L1_SET + 256)                // 53504  (single buffer)

// ---------------------------------------------------------------------------
// K2: merged layer-1 GEMM + h0 GEMM. Loaders are pure uint4 copies.
//  blocks [0,400):  l1 tile: xt=b>>1 (m0=xt*64), half=b&1; 4 K-chunks;
//                   epilogue relu + group-25 mean -> atomicAdd g_acc[0] (mh1)
//  blocks [400,464): h0 split-K: m0=(bid&7)*64, half=(bid>>3)&1, kz=bid>>4;
//                   1 K-chunk; atomicAdd g_acc[1] (+bias on kz==0)
// ---------------------------------------------------------------------------
__global__ __launch_bounds__(256, 2)
void k2_kernel(const float* __restrict__ bx1, const float* __restrict__ bn1)
{
    extern __shared__ char smraw[];
    uint32_t raw = smem_u32(smraw);
    uint32_t sb  = (raw + 255) & ~255u;
    char* base   = smraw + (sb - raw);

    const int tid = threadIdx.x, wid = tid >> 5, lane = tid & 31;
    const int g = lane >> 2, tg = lane & 3;
    const int b = blockIdx.x;

    const bool is_l1 = (b < 400);
    int m0, half, kz0, nch;
    const __nv_bfloat16 *Asrc_h, *Asrc_l;
    if (is_l1) {
        m0 = (b >> 1) * 64; half = b & 1; kz0 = 0; nch = 4;
        Asrc_h = half ? g_m2h : g_f1h;
        Asrc_l = half ? g_m2l : g_f1l;
    } else {
        const int bid = b - 400;
        m0 = (bid & 7) * 64; half = (bid >> 3) & 1; kz0 = bid >> 4; nch = 1;
        Asrc_h = half ? g_m1h : g_f0h;
        Asrc_l = half ? g_m1l : g_f0l;
    }
    const __nv_bfloat16* __restrict__ Wh = g_w1h + half * 32768;
    const __nv_bfloat16* __restrict__ Wl = g_w1l + half * 32768;
    const float* __restrict__ bias = half ? bn1 : bx1;

    const int ar = tid >> 2, k0e = (tid & 3) * 16;     // A copy mapping
    const int krow = tid >> 2, n0 = (tid & 3) * 32;    // B copy mapping

    auto load_chunk = [&](int c, int s) {
        char* AhS = base + s * L1_SET;
        char* AlS = AhS + L1_ASZ;
        char* BhS = AlS + L1_ASZ;
        char* BlS = BhS + L1_BSZ;
        size_t asrc = (size_t)(m0 + ar) * DIM + c * 64 + k0e;
        uint32_t ad = (uint32_t)ar * ASTR + (uint32_t)k0e * 2;
        *(uint4*)(AhS + ad)      = __ldg((const uint4*)(Asrc_h + asrc));
        *(uint4*)(AhS + ad + 16) = __ldg((const uint4*)(Asrc_h + asrc + 8));
        *(uint4*)(AlS + ad)      = __ldg((const uint4*)(Asrc_l + asrc));
        *(uint4*)(AlS + ad + 16) = __ldg((const uint4*)(Asrc_l + asrc + 8));
        size_t bsrc = (size_t)(c * 64 + krow) * HIDV + n0;
        uint32_t bd = (uint32_t)krow * BSTR + (uint32_t)n0 * 2;
#pragma unroll
        for (int q = 0; q < 4; ++q) {
            *(uint4*)(BhS + bd + q * 16) = __ldg((const uint4*)(Wh + bsrc + q * 8));
            *(uint4*)(BlS + bd + q * 16) = __ldg((const uint4*)(Wl + bsrc + q * 8));
        }
    };

    const int wm  = (wid & 3) * 16;
    const int wnl = (wid >> 2) * 64;
    float acc[8][4];
#pragma unroll
    for (int nt = 0; nt < 8; ++nt)
#pragma unroll
        for (int i = 0; i < 4; ++i) acc[nt][i] = 0.f;

    auto mma_chunk = [&](int s) {
        uint32_t Ab = sb + s * L1_SET;
        uint32_t Bb = Ab + 2 * L1_ASZ;
#pragma unroll
        for (int ks = 0; ks < 4; ++ks) {
            const int k0 = ks * 16;
            uint32_t ah[4], al[4];
            uint32_t ra = Ab + (uint32_t)(wm + (lane & 15)) * ASTR
                        + (uint32_t)(lane >> 4) * 16 + (uint32_t)k0 * 2;
            ldsm4(ah, ra);
            ldsm4(al, ra + L1_ASZ);
            uint32_t bhf[8][2], blf[8][2];
#pragma unroll
            for (int nt = 0; nt < 8; ++nt) {
                uint32_t rb = Bb + (uint32_t)(k0 + (lane & 15)) * BSTR
                            + (uint32_t)(wnl + nt * 8) * 2;
                ldsm2t(bhf[nt], rb);
                ldsm2t(blf[nt], rb + L1_BSZ);
            }
#pragma unroll
            for (int nt = 0; nt < 8; ++nt) mma16816(acc[nt], ah, bhf[nt]);
#pragma unroll
            for (int nt = 0; nt < 8; ++nt) mma16816(acc[nt], ah, blf[nt]);
#pragma unroll
            for (int nt = 0; nt < 8; ++nt) mma16816(acc[nt], al, bhf[nt]);
        }
    };

    load_chunk(kz0, 0);
    __syncthreads();
#pragma unroll 1
    for (int ci = 0; ci < nch; ++ci) {
        mma_chunk(ci & 1);
        if (ci + 1 < nch) load_chunk(kz0 + ci + 1, (ci + 1) & 1);
        __syncthreads();
    }

    if (is_l1) {
        // relu + bias -> smem stage -> group-25 column means -> mh1 atomics
        float* ep = (float*)base;      // 64 x 130 fp32
#pragma unroll
        for (int nt = 0; nt < 8; ++nt) {
            int c0 = wnl + nt * 8 + 2 * tg;
            float2 bv = *(const float2*)(bias + c0);
            int r0 = wm + g;
            ep[r0 * 130 + c0]           = fmaxf(acc[nt][0] + bv.x, 0.f);
            ep[r0 * 130 + c0 + 1]       = fmaxf(acc[nt][1] + bv.y, 0.f);
            ep[(r0 + 8) * 130 + c0]     = fmaxf(acc[nt][2] + bv.x, 0.f);
            ep[(r0 + 8) * 130 + c0 + 1] = fmaxf(acc[nt][3] + bv.y, 0.f);
        }
        __syncthreads();
        const int gbase = m0 / 25;
        for (int idx = tid; idx < 4 * 128; idx += 256) {
            int gi = idx >> 7, col = idx & 127;
            int gg = gbase + gi;
            int rs = gg * 25 - m0;      if (rs < 0)  rs = 0;
            int re = gg * 25 + 25 - m0; if (re > 64) re = 64;
            if (rs < re) {
                float s = 0.f;
                for (int r = rs; r < re; ++r) s += ep[r * 130 + col];
                atomicAdd(&g_acc[(size_t)gg * DIM + half * HIDV + col], s * (1.f / 25.f));
            }
        }
    } else {
        // h0 split-K accumulate (bias only from kz==0)
        float* h0p = g_acc + NB * DIM;
#pragma unroll
        for (int nt = 0; nt < 8; ++nt) {
            int c0 = wnl + nt * 8 + 2 * tg;
            float bvx = 0.f, bvy = 0.f;
            if (kz0 == 0) { float2 bv = *(const float2*)(bias + c0); bvx = bv.x; bvy = bv.y; }
            int r0 = m0 + wm + g;
            float* d0 = &h0p[(size_t)r0 * DIM + half * HIDV + c0];
            atomicAdd(d0,     acc[nt][0] + bvx);
            atomicAdd(d0 + 1, acc[nt][1] + bvy);
            float* d1 = &h0p[(size_t)(r0 + 8) * DIM + half * HIDV + c0];
            atomicAdd(d1,     acc[nt][2] + bvx);
            atomicAdd(d1 + 1, acc[nt][3] + bvy);
        }
    }
}

// ---------------------------------------------------------------------------
// K3: g0 = [relu(h0)@Wx2+bx2 ; mh1@Wn2+bn2], split-K (8,2,4). A split inline
// (only source still fp32); B from pre-split W2. atomicAdd into g_acc[2].
// ---------------------------------------------------------------------------
__global__ __launch_bounds__(256)
void g0_kernel(const float* __restrict__ bx2, const float* __restrict__ bn2)
{
    extern __shared__ char smraw[];
    uint32_t raw = smem_u32(smraw);
    uint32_t sb  = (raw + 255) & ~255u;
    char* base   = smraw + (sb - raw);
    char* AhS = base;
    char* AlS = AhS + L1_ASZ;
    char* BhS = AlS + L1_ASZ;
    char* BlS = BhS + L1_BSZ;

    const int tid = threadIdx.x, wid = tid >> 5, lane = tid & 31;
    const int g = lane >> 2, tg = lane & 3;
    const int m0 = blockIdx.x * 64;
    const int half = blockIdx.y;
    const int kz   = blockIdx.z;
    const float* __restrict__ Asrc = half ? g_acc : (g_acc + NB * DIM); // mh1 : h0
    const __nv_bfloat16* __restrict__ Wh = g_w2h + half * 32768;
    const __nv_bfloat16* __restrict__ Wl = g_w2l + half * 32768;
    const float* __restrict__ bias = half ? bn2 : bx2;

    {   // A: fp32 -> split (relu for half 0)
        const int ar = tid >> 2, k0e = (tid & 3) * 16;
        const float4* p = (const float4*)(Asrc + (size_t)(m0 + ar) * DIM + kz * 64 + k0e);
#pragma unroll
        for (int q = 0; q < 4; ++q) {
            float4 v = __ldg(p + q);
            if (half == 0) {
                v.x = fmaxf(v.x, 0.f); v.y = fmaxf(v.y, 0.f);
                v.z = fmaxf(v.z, 0.f); v.w = fmaxf(v.w, 0.f);
            }
            uint32_t o = (uint32_t)ar * ASTR + (uint32_t)(k0e + q * 4) * 2;
            split_store(AhS + o, AlS + o, v);
        }
    }
    {   // B: pure copies
        const int krow = tid >> 2, n0 = (tid & 3) * 32;
        size_t bsrc = (size_t)(kz * 64 + krow) * HIDV + n0;
        uint32_t bd = (uint32_t)krow * BSTR + (uint32_t)n0 * 2;
#pragma unroll
        for (int q = 0; q < 4; ++q) {
            *(uint4*)(BhS + bd + q * 16) = __ldg((const uint4*)(Wh + bsrc + q * 8));
            *(uint4*)(BlS + bd + q * 16) = __ldg((const uint4*)(Wl + bsrc + q * 8));
        }
    }
    __syncthreads();

    const int wm  = (wid & 3) * 16;
    const int wnl = (wid >> 2) * 64;
    float acc[8][4];
#pragma unroll
    for (int nt = 0; nt < 8; ++nt)
#pragma unroll
        for (int i = 0; i < 4; ++i) acc[nt][i] = 0.f;

    const uint32_t Ab = sb, Bb = sb + 2 * L1_ASZ;
#pragma unroll
    for (int ks = 0; ks < 4; ++ks) {
        const int k0 = ks * 16;
        uint32_t ah[4], al[4];
        uint32_t ra = Ab + (uint32_t)(wm + (lane & 15)) * ASTR
                    + (uint32_t)(lane >> 4) * 16 + (uint32_t)k0 * 2;
        ldsm4(ah, ra);
        ldsm4(al, ra + L1_ASZ);
        uint32_t bhf[8][2], blf[8][2];
#pragma unroll
        for (int nt = 0; nt < 8; ++nt) {
            uint32_t rb = Bb + (uint32_t)(k0 + (lane & 15)) * BSTR
                        + (uint32_t)(wnl + nt * 8) * 2;
            ldsm2t(bhf[nt], rb);
            ldsm2t(blf[nt], rb + L1_BSZ);
        }
#pragma unroll
        for (int nt = 0; nt < 8; ++nt) mma16816(acc[nt], ah, bhf[nt]);
#pragma unroll
        for (int nt = 0; nt < 8; ++nt) mma16816(acc[nt], ah, blf[nt]);
#pragma unroll
        for (int nt = 0; nt < 8; ++nt) mma16816(acc[nt], al, bhf[nt]);
    }

    float* g0p = g_acc + 2 * NB * DIM;
#pragma unroll
    for (int nt = 0; nt < 8; ++nt) {
        int c0 = wnl + nt * 8 + 2 * tg;
        float bvx = 0.f, bvy = 0.f;
        if (kz == 0) { float2 bv = *(const float2*)(bias + c0); bvx = bv.x; bvy = bv.y; }
        int r0 = m0 + wm + g;
        float* d0 = &g0p[(size_t)r0 * DIM + half * HIDV + c0];
        atomicAdd(d0,     acc[nt][0] + bvx);
        atomicAdd(d0 + 1, acc[nt][1] + bvy);
        float* d1 = &g0p[(size_t)(r0 + 8) * DIM + half * HIDV + c0];
        atomicAdd(d1,     acc[nt][2] + bvx);
        atomicAdd(d1 + 1, acc[nt][3] + bvy);
    }
}

// ---------------------------------------------------------------------------
// K4: row-normalize g0 then FC [256 -> 7].
// ---------------------------------------------------------------------------
__global__ __launch_bounds__(256)
void final_kernel(const float* __restrict__ Wfc, const float* __restrict__ bfc,
                  float* __restrict__ out)
{
    const int row = blockIdx.x;
    __shared__ float s[DIM];
    __shared__ float red[8];
    __shared__ float s_inv;
    const int t = threadIdx.x;
    const float* g0p = g_acc + 2 * NB * DIM;

    float v = g0p[(size_t)row * DIM + t];
    s[t] = v;
    float sq = v * v;
#pragma unroll
    for (int o = 16; o; o >>= 1) sq += __shfl_xor_sync(0xFFFFFFFFu, sq, o);
    if ((t & 31) == 0) red[t >> 5] = sq;
    __syncthreads();
    if (t == 0) {
        float tot = 0.f;
#pragma unroll
        for (int i = 0; i < 8; ++i) tot += red[i];
        s_inv = 1.f / fmaxf(sqrtf(tot), 1e-12f);
    }
    __syncthreads();
    const float inv = s_inv;

    const int w = t >> 5, l = t & 31;
    if (w < 7) {
        float acc = 0.f;
#pragma unroll
        for (int k = l; k < DIM; k += 32)
            acc = fmaf(s[k], __ldg(&Wfc[k * 7 + w]), acc);
#pragma unroll
        for (int o = 16; o; o >>= 1) acc += __shfl_xor_sync(0xFFFFFFFFu, acc, o);
        if (l == 0) out[row * 7 + w] = acc * inv + bfc[w];
    }
}

// ---------------------------------------------------------------------------
extern "C" void kernel_launch(void* const* d_in, const int* in_sizes, int n_in,
                              void* d_out, int out_size)
{
    const int*   ids   = (const int*)  d_in[0];
    const int*   ids1  = (const int*)  d_in[1];
    const int*   ids2  = (const int*)  d_in[2];
    const float* feats = (const float*)d_in[3];
    const float* Wx1   = (const float*)d_in[4];
    const float* bx1   = (const float*)d_in[5];
    const float* Wn1   = (const float*)d_in[6];
    const float* bn1   = (const float*)d_in[7];
    const float* Wx2   = (const float*)d_in[8];
    const float* bx2   = (const float*)d_in[9];
    const float* Wn2   = (const float*)d_in[10];
    const float* bn2   = (const float*)d_in[11];
    const float* Wfc   = (const float*)d_in[12];
    const float* bfc   = (const float*)d_in[13];
    float* out = (float*)d_out;

    cudaFuncSetAttribute(k2_kernel, cudaFuncAttributeMaxDynamicSharedMemorySize, SM_K2);
    cudaFuncSetAttribute(g0_kernel, cudaFuncAttributeMaxDynamicSharedMemorySize, SM_K3);

    // K1: all gathers/means/splits + zeroing (one launch)
    prep_kernel<<<3416, 256>>>(feats, ids, ids1, ids2, Wx1, Wn1, Wx2, Wn2);
    // K2: l1 GEMM (-> mh1) + h0 GEMM (merged)
    k2_kernel<<<464, 256, SM_K2>>>(bx1, bn1);
    // K3: g0 GEMM
    g0_kernel<<<dim3(8, 2, 4), 256, SM_K3>>>(bx2, bn2);
    // K4: normalize + FC
    final_kernel<<<NB, 256>>>(Wfc, bfc, out);
}